// round 5
// baseline (speedup 1.0000x reference)
#include <cuda_runtime.h>
#include <math.h>

// ---------------------------------------------------------------------------
// LSTM_88716844466217 : B=64, ILEN=256, TLEN=64 (T=320), IDIM=512, HDIM=1024,
// ODIM=128. fp32 throughout, packed fma.rn.f32x2 over K-pairs for 2x fp32 rate.
// ---------------------------------------------------------------------------

constexpr int BSZ  = 64;
constexpr int ILEN = 256;
constexpr int TLEN = 64;
constexpr int TT   = ILEN + TLEN;   // 320
constexpr int IDIM = 512;
constexpr int HDIM = 1024;
constexpr int G4   = 4 * HDIM;      // 4096
constexpr int ODIM = 128;

// Scratch (device globals: allocation-free per harness rules)
__device__ float g_xproj[(size_t)BSZ * ILEN * G4];   // [b*ILEN+t][4096], bias included (268 MB)
__device__ float g_h0[BSZ * HDIM];
__device__ float g_h1[BSZ * HDIM];
__device__ float g_c [BSZ * HDIM];
__device__ float g_hs[(size_t)TLEN * BSZ * HDIM];    // h for t in [ILEN, TT)

#define DINL __device__ __forceinline__

DINL void ffma2(unsigned long long &d, unsigned long long a, unsigned long long b) {
    asm("fma.rn.f32x2 %0, %1, %2, %0;" : "+l"(d) : "l"(a), "l"(b));
}
DINL float pair_sum(unsigned long long v) {
    return __uint_as_float((unsigned)(v & 0xffffffffu)) +
           __uint_as_float((unsigned)(v >> 32));
}
DINL float sigmoidf_(float x) { return 1.0f / (1.0f + expf(-x)); }

// MAC over one K-tile. As[BM][SKC], Bs[BN][SKC] (K-contiguous rows, stride SKC=KC+2).
// Thread (tr,tc) owns rows {tr+16*i} and cols {tc+16*j}. acc pairs = (even-k, odd-k) sums.
template<int TM, int TN, int KC, int SKC>
DINL void mac_tile(const float* __restrict__ As, const float* __restrict__ Bs,
                   int tr, int tc, unsigned long long (&acc)[TM][TN]) {
#pragma unroll
    for (int kp = 0; kp < KC / 2; ++kp) {
        unsigned long long a2[TM], b2[TN];
#pragma unroll
        for (int i = 0; i < TM; ++i)
            a2[i] = *reinterpret_cast<const unsigned long long*>(As + (tr + 16 * i) * SKC + 2 * kp);
#pragma unroll
        for (int j = 0; j < TN; ++j)
            b2[j] = *reinterpret_cast<const unsigned long long*>(Bs + (tc + 16 * j) * SKC + 2 * kp);
#pragma unroll
        for (int i = 0; i < TM; ++i)
#pragma unroll
            for (int j = 0; j < TN; ++j)
                ffma2(acc[i][j], a2[i], b2[j]);
    }
}

// store a float4 into smem (rows only 8B-aligned due to SKC padding)
DINL void sts4_as_2x2(float* p, float4 q) {
    *reinterpret_cast<float2*>(p)     = make_float2(q.x, q.y);
    *reinterpret_cast<float2*>(p + 2) = make_float2(q.z, q.w);
}

// ---------------------------------------------------------------------------
// init: zero h(t=0) and c
// ---------------------------------------------------------------------------
__global__ void init_kernel() {
    int i = blockIdx.x * blockDim.x + threadIdx.x;
    if (i < BSZ * HDIM) { g_h0[i] = 0.0f; g_c[i] = 0.0f; }
}

// ---------------------------------------------------------------------------
// x_proj GEMM: C[16384,4096] = inp[16384,512] @ w_ih[4096,512]^T + bias
// BM=128, BN=64, KC=32, 256 thr, TM=8, TN=4
// ---------------------------------------------------------------------------
__global__ __launch_bounds__(256) void xproj_kernel(const float* __restrict__ inp,
                                                    const float* __restrict__ w_ih,
                                                    const float* __restrict__ bias) {
    constexpr int BM = 128, BN = 64, KC = 32, SKC = KC + 2, TM = 8, TN = 4;
    __shared__ float As[BM * SKC];
    __shared__ float Bs[BN * SKC];
    const int tid = threadIdx.x;
    const int tr = tid >> 4, tc = tid & 15;
    const int row0 = blockIdx.y * BM;
    const int col0 = blockIdx.x * BN;

    unsigned long long acc[TM][TN];
#pragma unroll
    for (int i = 0; i < TM; ++i)
#pragma unroll
        for (int j = 0; j < TN; ++j) acc[i][j] = 0ull;

    for (int k0 = 0; k0 < IDIM; k0 += KC) {
#pragma unroll
        for (int v = 0; v < 4; ++v) {           // A: 128*32/4 = 1024 float4
            int id = tid + v * 256;
            int r = id >> 3, kq = id & 7;       // KC/4 = 8
            float4 q = *reinterpret_cast<const float4*>(
                inp + (size_t)(row0 + r) * IDIM + k0 + kq * 4);
            sts4_as_2x2(As + r * SKC + kq * 4, q);
        }
#pragma unroll
        for (int v = 0; v < 2; ++v) {           // B: 64*32/4 = 512 float4
            int id = tid + v * 256;
            int r = id >> 3, kq = id & 7;
            float4 q = *reinterpret_cast<const float4*>(
                w_ih + (size_t)(col0 + r) * IDIM + k0 + kq * 4);
            sts4_as_2x2(Bs + r * SKC + kq * 4, q);
        }
        __syncthreads();
        mac_tile<TM, TN, KC, SKC>(As, Bs, tr, tc, acc);
        __syncthreads();
    }

#pragma unroll
    for (int j = 0; j < TN; ++j) {
        int c = col0 + tc + 16 * j;
        float bv = bias[c];
#pragma unroll
        for (int i = 0; i < TM; ++i) {
            int r = row0 + tr + 16 * i;
            g_xproj[(size_t)r * G4 + c] = pair_sum(acc[i][j]) + bv;
        }
    }
}

// ---------------------------------------------------------------------------
// One LSTM step: gates = x_proj[t] + h @ w_hh^T, then elementwise update.
// 128 blocks; block bx owns hidden cols [bx*8, bx*8+8) across ALL 4 gates
// (32 w_hh rows), so the pointwise update fuses in-block. h double-buffered.
// BM=64(batch), BN=32, KC=64, 256 thr, TM=4, TN=2.
// Local col lcol = gate*8 + jj  <->  w_hh row gate*HDIM + j0 + jj.
// ---------------------------------------------------------------------------
__global__ __launch_bounds__(256) void step_kernel(const float* __restrict__ w_hh,
                                                   const float* __restrict__ bias,
                                                   int t) {
    constexpr int BM = 64, BN = 32, KC = 64, SKC = KC + 2, TM = 4, TN = 2;
    __shared__ float As[BM * SKC];   // 4224 floats; reused as gate buffer after GEMM
    __shared__ float Bs[BN * SKC];

    const float* __restrict__ hin  = (t & 1) ? g_h1 : g_h0;
    float* __restrict__ hout       = (t & 1) ? g_h0 : g_h1;

    const int tid = threadIdx.x;
    const int tr = tid >> 4, tc = tid & 15;
    const int j0 = blockIdx.x * 8;

    unsigned long long acc[TM][TN];
#pragma unroll
    for (int i = 0; i < TM; ++i)
#pragma unroll
        for (int j = 0; j < TN; ++j) acc[i][j] = 0ull;

    for (int k0 = 0; k0 < HDIM; k0 += KC) {
#pragma unroll
        for (int v = 0; v < 4; ++v) {           // h: 64*64/4 = 1024 float4
            int id = tid + v * 256;
            int r = id >> 4, kq = id & 15;      // KC/4 = 16
            float4 q = *reinterpret_cast<const float4*>(
                hin + (size_t)r * HDIM + k0 + kq * 4);
            sts4_as_2x2(As + r * SKC + kq * 4, q);
        }
#pragma unroll
        for (int v = 0; v < 2; ++v) {           // w_hh: 32*64/4 = 512 float4
            int id = tid + v * 256;
            int r = id >> 4, kq = id & 15;
            int grow = (r >> 3) * HDIM + j0 + (r & 7);
            float4 q = *reinterpret_cast<const float4*>(
                w_hh + (size_t)grow * HDIM + k0 + kq * 4);
            sts4_as_2x2(Bs + r * SKC + kq * 4, q);
        }
        __syncthreads();
        mac_tile<TM, TN, KC, SKC>(As, Bs, tr, tc, acc);
        __syncthreads();
    }

    // dump gate pre-activations (recurrent part) to smem, reuse As region
    float* gbuf = As;                            // stride 33, [b][lcol]
#pragma unroll
    for (int i = 0; i < TM; ++i)
#pragma unroll
        for (int j = 0; j < TN; ++j)
            gbuf[(tr + 16 * i) * 33 + (tc + 16 * j)] = pair_sum(acc[i][j]);
    __syncthreads();

    // pointwise LSTM update: 64 b x 8 jj = 512 elements
#pragma unroll
    for (int e0 = 0; e0 < 2; ++e0) {
        int e  = tid + e0 * 256;
        int b  = e >> 3;
        int jj = e & 7;
        float pre[4];
#pragma unroll
        for (int g = 0; g < 4; ++g) {
            int col = g * HDIM + j0 + jj;
            float x = (t < ILEN) ? g_xproj[((size_t)b * ILEN + t) * G4 + col]
                                 : bias[col];   // padded steps: input = 0 -> x_proj = bias
            pre[g] = gbuf[b * 33 + g * 8 + jj] + x;
        }
        float ig = sigmoidf_(pre[0]);
        float fg = sigmoidf_(pre[1]);
        float gg = tanhf(pre[2]);
        float og = sigmoidf_(pre[3]);
        int idx  = b * HDIM + j0 + jj;
        float cn = fg * g_c[idx] + ig * gg;
        g_c[idx] = cn;
        float hn = og * tanhf(cn);
        hout[idx] = hn;
        if (t >= ILEN)
            g_hs[(size_t)(t - ILEN) * (BSZ * HDIM) + idx] = hn;
    }
}

// ---------------------------------------------------------------------------
// classifier: out[b][tt][o] = sigmoid(hs[tt][b] . clf_w[o] + clf_b[o])
// rows = tt*64 + b (hs layout). BM=64, BN=64, KC=64, TM=4, TN=4. grid (2, 64).
// ---------------------------------------------------------------------------
__global__ __launch_bounds__(256) void clf_kernel(const float* __restrict__ clf_w,
                                                  const float* __restrict__ clf_b,
                                                  float* __restrict__ out) {
    constexpr int BM = 64, BN = 64, KC = 64, SKC = KC + 2, TM = 4, TN = 4;
    __shared__ float As[BM * SKC];
    __shared__ float Bs[BN * SKC];
    const int tid = threadIdx.x;
    const int tr = tid >> 4, tc = tid & 15;
    const int row0 = blockIdx.y * BM;
    const int col0 = blockIdx.x * BN;

    unsigned long long acc[TM][TN];
#pragma unroll
    for (int i = 0; i < TM; ++i)
#pragma unroll
        for (int j = 0; j < TN; ++j) acc[i][j] = 0ull;

    for (int k0 = 0; k0 < HDIM; k0 += KC) {
#pragma unroll
        for (int v = 0; v < 4; ++v) {           // hs rows: 64*64/4 = 1024 float4
            int id = tid + v * 256;
            int r = id >> 4, kq = id & 15;
            float4 q = *reinterpret_cast<const float4*>(
                g_hs + (size_t)(row0 + r) * HDIM + k0 + kq * 4);
            sts4_as_2x2(As + r * SKC + kq * 4, q);
        }
#pragma unroll
        for (int v = 0; v < 4; ++v) {           // clf_w rows
            int id = tid + v * 256;
            int r = id >> 4, kq = id & 15;
            float4 q = *reinterpret_cast<const float4*>(
                clf_w + (size_t)(col0 + r) * HDIM + k0 + kq * 4);
            sts4_as_2x2(Bs + r * SKC + kq * 4, q);
        }
        __syncthreads();
        mac_tile<TM, TN, KC, SKC>(As, Bs, tr, tc, acc);
        __syncthreads();
    }

#pragma unroll
    for (int j = 0; j < TN; ++j) {
        int o = col0 + tc + 16 * j;
        float bv = clf_b[o];
#pragma unroll
        for (int i = 0; i < TM; ++i) {
            int r  = row0 + tr + 16 * i;
            int tt = r >> 6;        // r / 64
            int b  = r & 63;
            out[((size_t)b * TLEN + tt) * ODIM + o] = sigmoidf_(pair_sum(acc[i][j]) + bv);
        }
    }
}

// ---------------------------------------------------------------------------
// launch (graph-capturable: kernel launches only, default stream)
// Inputs (metadata order): inp, tlen, w_ih, w_hh, b, clf_w, clf_b
// ---------------------------------------------------------------------------
extern "C" void kernel_launch(void* const* d_in, const int* in_sizes, int n_in,
                              void* d_out, int out_size) {
    const float* inp   = (const float*)d_in[0];
    // d_in[1] = tlen (int32) — fixed at 64, unused
    const float* w_ih  = (const float*)d_in[2];
    const float* w_hh  = (const float*)d_in[3];
    const float* bias  = (const float*)d_in[4];
    const float* clf_w = (const float*)d_in[5];
    const float* clf_b = (const float*)d_in[6];
    float* out = (float*)d_out;

    init_kernel<<<(BSZ * HDIM + 255) / 256, 256>>>();
    xproj_kernel<<<dim3(G4 / 64, (BSZ * ILEN) / 128), 256>>>(inp, w_ih, bias);
    for (int t = 0; t < TT; ++t)
        step_kernel<<<HDIM / 8, 256>>>(w_hh, bias, t);
    clf_kernel<<<dim3(ODIM / 64, (TLEN * BSZ) / 64), 256>>>(clf_w, clf_b, out);
}

// round 6
// speedup vs baseline: 1.0000x; 1.0000x over previous
#include <cuda_runtime.h>
#include <math.h>

// ---------------------------------------------------------------------------
// LSTM_88716844466217 : B=64, ILEN=256, TLEN=64 (T=320), IDIM=512, HDIM=1024,
// ODIM=128. fp32 throughout, packed fma.rn.f32x2 over K-pairs for 2x fp32 rate.
// ---------------------------------------------------------------------------

constexpr int BSZ  = 64;
constexpr int ILEN = 256;
constexpr int TLEN = 64;
constexpr int TT   = ILEN + TLEN;   // 320
constexpr int IDIM = 512;
constexpr int HDIM = 1024;
constexpr int G4   = 4 * HDIM;      // 4096
constexpr int ODIM = 128;

// Scratch (device globals: allocation-free per harness rules)
__device__ float g_xproj[(size_t)BSZ * ILEN * G4];   // [b*ILEN+t][4096], bias included (268 MB)
__device__ float g_h0[BSZ * HDIM];
__device__ float g_h1[BSZ * HDIM];
__device__ float g_c [BSZ * HDIM];
__device__ float g_hs[(size_t)TLEN * BSZ * HDIM];    // h for t in [ILEN, TT)

#define DINL __device__ __forceinline__

DINL void ffma2(unsigned long long &d, unsigned long long a, unsigned long long b) {
    asm("fma.rn.f32x2 %0, %1, %2, %0;" : "+l"(d) : "l"(a), "l"(b));
}
DINL float pair_sum(unsigned long long v) {
    return __uint_as_float((unsigned)(v & 0xffffffffu)) +
           __uint_as_float((unsigned)(v >> 32));
}
DINL float sigmoidf_(float x) { return 1.0f / (1.0f + expf(-x)); }

// MAC over one K-tile. As[BM][SKC], Bs[BN][SKC] (K-contiguous rows, stride SKC=KC+2).
// Thread (tr,tc) owns rows {tr+16*i} and cols {tc+16*j}. acc pairs = (even-k, odd-k) sums.
template<int TM, int TN, int KC, int SKC>
DINL void mac_tile(const float* __restrict__ As, const float* __restrict__ Bs,
                   int tr, int tc, unsigned long long (&acc)[TM][TN]) {
#pragma unroll
    for (int kp = 0; kp < KC / 2; ++kp) {
        unsigned long long a2[TM], b2[TN];
#pragma unroll
        for (int i = 0; i < TM; ++i)
            a2[i] = *reinterpret_cast<const unsigned long long*>(As + (tr + 16 * i) * SKC + 2 * kp);
#pragma unroll
        for (int j = 0; j < TN; ++j)
            b2[j] = *reinterpret_cast<const unsigned long long*>(Bs + (tc + 16 * j) * SKC + 2 * kp);
#pragma unroll
        for (int i = 0; i < TM; ++i)
#pragma unroll
            for (int j = 0; j < TN; ++j)
                ffma2(acc[i][j], a2[i], b2[j]);
    }
}

// store a float4 into smem (rows only 8B-aligned due to SKC padding)
DINL void sts4_as_2x2(float* p, float4 q) {
    *reinterpret_cast<float2*>(p)     = make_float2(q.x, q.y);
    *reinterpret_cast<float2*>(p + 2) = make_float2(q.z, q.w);
}

// ---------------------------------------------------------------------------
// init: zero h(t=0) and c
// ---------------------------------------------------------------------------
__global__ void init_kernel() {
    int i = blockIdx.x * blockDim.x + threadIdx.x;
    if (i < BSZ * HDIM) { g_h0[i] = 0.0f; g_c[i] = 0.0f; }
}

// ---------------------------------------------------------------------------
// x_proj GEMM: C[16384,4096] = inp[16384,512] @ w_ih[4096,512]^T + bias
// BM=128, BN=64, KC=32, 256 thr, TM=8, TN=4
// ---------------------------------------------------------------------------
__global__ __launch_bounds__(256) void xproj_kernel(const float* __restrict__ inp,
                                                    const float* __restrict__ w_ih,
                                                    const float* __restrict__ bias) {
    constexpr int BM = 128, BN = 64, KC = 32, SKC = KC + 2, TM = 8, TN = 4;
    __shared__ float As[BM * SKC];
    __shared__ float Bs[BN * SKC];
    const int tid = threadIdx.x;
    const int tr = tid >> 4, tc = tid & 15;
    const int row0 = blockIdx.y * BM;
    const int col0 = blockIdx.x * BN;

    unsigned long long acc[TM][TN];
#pragma unroll
    for (int i = 0; i < TM; ++i)
#pragma unroll
        for (int j = 0; j < TN; ++j) acc[i][j] = 0ull;

    for (int k0 = 0; k0 < IDIM; k0 += KC) {
#pragma unroll
        for (int v = 0; v < 4; ++v) {           // A: 128*32/4 = 1024 float4
            int id = tid + v * 256;
            int r = id >> 3, kq = id & 7;       // KC/4 = 8
            float4 q = *reinterpret_cast<const float4*>(
                inp + (size_t)(row0 + r) * IDIM + k0 + kq * 4);
            sts4_as_2x2(As + r * SKC + kq * 4, q);
        }
#pragma unroll
        for (int v = 0; v < 2; ++v) {           // B: 64*32/4 = 512 float4
            int id = tid + v * 256;
            int r = id >> 3, kq = id & 7;
            float4 q = *reinterpret_cast<const float4*>(
                w_ih + (size_t)(col0 + r) * IDIM + k0 + kq * 4);
            sts4_as_2x2(Bs + r * SKC + kq * 4, q);
        }
        __syncthreads();
        mac_tile<TM, TN, KC, SKC>(As, Bs, tr, tc, acc);
        __syncthreads();
    }

#pragma unroll
    for (int j = 0; j < TN; ++j) {
        int c = col0 + tc + 16 * j;
        float bv = bias[c];
#pragma unroll
        for (int i = 0; i < TM; ++i) {
            int r = row0 + tr + 16 * i;
            g_xproj[(size_t)r * G4 + c] = pair_sum(acc[i][j]) + bv;
        }
    }
}

// ---------------------------------------------------------------------------
// One LSTM step: gates = x_proj[t] + h @ w_hh^T, then elementwise update.
// 128 blocks; block bx owns hidden cols [bx*8, bx*8+8) across ALL 4 gates
// (32 w_hh rows), so the pointwise update fuses in-block. h double-buffered.
// BM=64(batch), BN=32, KC=64, 256 thr, TM=4, TN=2.
// Local col lcol = gate*8 + jj  <->  w_hh row gate*HDIM + j0 + jj.
// ---------------------------------------------------------------------------
__global__ __launch_bounds__(256) void step_kernel(const float* __restrict__ w_hh,
                                                   const float* __restrict__ bias,
                                                   int t) {
    constexpr int BM = 64, BN = 32, KC = 64, SKC = KC + 2, TM = 4, TN = 2;
    __shared__ float As[BM * SKC];   // 4224 floats; reused as gate buffer after GEMM
    __shared__ float Bs[BN * SKC];

    const float* __restrict__ hin  = (t & 1) ? g_h1 : g_h0;
    float* __restrict__ hout       = (t & 1) ? g_h0 : g_h1;

    const int tid = threadIdx.x;
    const int tr = tid >> 4, tc = tid & 15;
    const int j0 = blockIdx.x * 8;

    unsigned long long acc[TM][TN];
#pragma unroll
    for (int i = 0; i < TM; ++i)
#pragma unroll
        for (int j = 0; j < TN; ++j) acc[i][j] = 0ull;

    for (int k0 = 0; k0 < HDIM; k0 += KC) {
#pragma unroll
        for (int v = 0; v < 4; ++v) {           // h: 64*64/4 = 1024 float4
            int id = tid + v * 256;
            int r = id >> 4, kq = id & 15;      // KC/4 = 16
            float4 q = *reinterpret_cast<const float4*>(
                hin + (size_t)r * HDIM + k0 + kq * 4);
            sts4_as_2x2(As + r * SKC + kq * 4, q);
        }
#pragma unroll
        for (int v = 0; v < 2; ++v) {           // w_hh: 32*64/4 = 512 float4
            int id = tid + v * 256;
            int r = id >> 4, kq = id & 15;
            int grow = (r >> 3) * HDIM + j0 + (r & 7);
            float4 q = *reinterpret_cast<const float4*>(
                w_hh + (size_t)grow * HDIM + k0 + kq * 4);
            sts4_as_2x2(Bs + r * SKC + kq * 4, q);
        }
        __syncthreads();
        mac_tile<TM, TN, KC, SKC>(As, Bs, tr, tc, acc);
        __syncthreads();
    }

    // dump gate pre-activations (recurrent part) to smem, reuse As region
    float* gbuf = As;                            // stride 33, [b][lcol]
#pragma unroll
    for (int i = 0; i < TM; ++i)
#pragma unroll
        for (int j = 0; j < TN; ++j)
            gbuf[(tr + 16 * i) * 33 + (tc + 16 * j)] = pair_sum(acc[i][j]);
    __syncthreads();

    // pointwise LSTM update: 64 b x 8 jj = 512 elements
#pragma unroll
    for (int e0 = 0; e0 < 2; ++e0) {
        int e  = tid + e0 * 256;
        int b  = e >> 3;
        int jj = e & 7;
        float pre[4];
#pragma unroll
        for (int g = 0; g < 4; ++g) {
            int col = g * HDIM + j0 + jj;
            float x = (t < ILEN) ? g_xproj[((size_t)b * ILEN + t) * G4 + col]
                                 : bias[col];   // padded steps: input = 0 -> x_proj = bias
            pre[g] = gbuf[b * 33 + g * 8 + jj] + x;
        }
        float ig = sigmoidf_(pre[0]);
        float fg = sigmoidf_(pre[1]);
        float gg = tanhf(pre[2]);
        float og = sigmoidf_(pre[3]);
        int idx  = b * HDIM + j0 + jj;
        float cn = fg * g_c[idx] + ig * gg;
        g_c[idx] = cn;
        float hn = og * tanhf(cn);
        hout[idx] = hn;
        if (t >= ILEN)
            g_hs[(size_t)(t - ILEN) * (BSZ * HDIM) + idx] = hn;
    }
}

// ---------------------------------------------------------------------------
// classifier: out[b][tt][o] = sigmoid(hs[tt][b] . clf_w[o] + clf_b[o])
// rows = tt*64 + b (hs layout). BM=64, BN=64, KC=64, TM=4, TN=4. grid (2, 64).
// ---------------------------------------------------------------------------
__global__ __launch_bounds__(256) void clf_kernel(const float* __restrict__ clf_w,
                                                  const float* __restrict__ clf_b,
                                                  float* __restrict__ out) {
    constexpr int BM = 64, BN = 64, KC = 64, SKC = KC + 2, TM = 4, TN = 4;
    __shared__ float As[BM * SKC];
    __shared__ float Bs[BN * SKC];
    const int tid = threadIdx.x;
    const int tr = tid >> 4, tc = tid & 15;
    const int row0 = blockIdx.y * BM;
    const int col0 = blockIdx.x * BN;

    unsigned long long acc[TM][TN];
#pragma unroll
    for (int i = 0; i < TM; ++i)
#pragma unroll
        for (int j = 0; j < TN; ++j) acc[i][j] = 0ull;

    for (int k0 = 0; k0 < HDIM; k0 += KC) {
#pragma unroll
        for (int v = 0; v < 4; ++v) {           // hs rows: 64*64/4 = 1024 float4
            int id = tid + v * 256;
            int r = id >> 4, kq = id & 15;
            float4 q = *reinterpret_cast<const float4*>(
                g_hs + (size_t)(row0 + r) * HDIM + k0 + kq * 4);
            sts4_as_2x2(As + r * SKC + kq * 4, q);
        }
#pragma unroll
        for (int v = 0; v < 4; ++v) {           // clf_w rows
            int id = tid + v * 256;
            int r = id >> 4, kq = id & 15;
            float4 q = *reinterpret_cast<const float4*>(
                clf_w + (size_t)(col0 + r) * HDIM + k0 + kq * 4);
            sts4_as_2x2(Bs + r * SKC + kq * 4, q);
        }
        __syncthreads();
        mac_tile<TM, TN, KC, SKC>(As, Bs, tr, tc, acc);
        __syncthreads();
    }

#pragma unroll
    for (int j = 0; j < TN; ++j) {
        int o = col0 + tc + 16 * j;
        float bv = clf_b[o];
#pragma unroll
        for (int i = 0; i < TM; ++i) {
            int r  = row0 + tr + 16 * i;
            int tt = r >> 6;        // r / 64
            int b  = r & 63;
            out[((size_t)b * TLEN + tt) * ODIM + o] = sigmoidf_(pair_sum(acc[i][j]) + bv);
        }
    }
}

// ---------------------------------------------------------------------------
// launch (graph-capturable: kernel launches only, default stream)
// Inputs (metadata order): inp, tlen, w_ih, w_hh, b, clf_w, clf_b
// ---------------------------------------------------------------------------
extern "C" void kernel_launch(void* const* d_in, const int* in_sizes, int n_in,
                              void* d_out, int out_size) {
    const float* inp   = (const float*)d_in[0];
    // d_in[1] = tlen (int32) — fixed at 64, unused
    const float* w_ih  = (const float*)d_in[2];
    const float* w_hh  = (const float*)d_in[3];
    const float* bias  = (const float*)d_in[4];
    const float* clf_w = (const float*)d_in[5];
    const float* clf_b = (const float*)d_in[6];
    float* out = (float*)d_out;

    init_kernel<<<(BSZ * HDIM + 255) / 256, 256>>>();
    xproj_kernel<<<dim3(G4 / 64, (BSZ * ILEN) / 128), 256>>>(inp, w_ih, bias);
    for (int t = 0; t < TT; ++t)
        step_kernel<<<HDIM / 8, 256>>>(w_hh, bias, t);
    clf_kernel<<<dim3(ODIM / 64, (TLEN * BSZ) / 64), 256>>>(clf_w, clf_b, out);
}

// round 7
// speedup vs baseline: 1.3120x; 1.3119x over previous
#include <cuda_runtime.h>
#include <math.h>
#include <stdint.h>

// ---------------------------------------------------------------------------
// LSTM_88716844466217 : B=64, ILEN=256, TLEN=64 (T=320), IDIM=512, HDIM=1024,
// ODIM=128. fp32, packed fma.rn.f32x2. R7: persistent recurrent kernel with
// SMEM-resident w_hh slice, cp.async h streaming, register-resident c,
// K-split 512-thread blocks, software grid barrier.
// ---------------------------------------------------------------------------

constexpr int BSZ  = 64;
constexpr int ILEN = 256;
constexpr int TLEN = 64;
constexpr int TT   = ILEN + TLEN;   // 320
constexpr int IDIM = 512;
constexpr int HDIM = 1024;
constexpr int G4   = 4 * HDIM;      // 4096
constexpr int ODIM = 128;
constexpr int NBLK = 128;           // persistent blocks (1/SM, all resident)

// Scratch (device globals: allocation-free per harness rules)
__device__ float g_xproj[(size_t)BSZ * ILEN * G4];   // [b*ILEN+t][4096], bias included
__device__ float g_h0[BSZ * HDIM];
__device__ float g_h1[BSZ * HDIM];
__device__ float g_hs[(size_t)TLEN * BSZ * HDIM];    // h for t in [ILEN, TT)
__device__ unsigned g_arrive;                         // grid barrier counter

#define DINL __device__ __forceinline__

DINL void ffma2(unsigned long long &d, unsigned long long a, unsigned long long b) {
    asm("fma.rn.f32x2 %0, %1, %2, %0;" : "+l"(d) : "l"(a), "l"(b));
}
DINL float pair_sum(unsigned long long v) {
    return __uint_as_float((unsigned)(v & 0xffffffffu)) +
           __uint_as_float((unsigned)(v >> 32));
}
DINL float sigmoidf_(float x) { return 1.0f / (1.0f + __expf(-x)); }

DINL void cp_async16(uint32_t saddr, const float* gptr) {
    asm volatile("cp.async.cg.shared.global [%0], [%1], 16;" :: "r"(saddr), "l"(gptr));
}
DINL void cp_commit() { asm volatile("cp.async.commit_group;"); }
template<int N> DINL void cp_wait() { asm volatile("cp.async.wait_group %0;" :: "n"(N)); }

// Generic float4 (LDS.128) MAC: A rows tr+16i, B rows tc+16j, NQ quads of k.
// Row strides ≡ 4 banks mod 32 => conflict-free within 8-lane phases.
template<int TM, int TN, int NQ, int AST, int BST>
DINL void mac_f4(const float* __restrict__ Ap, const float* __restrict__ Bp,
                 int tr, int tc, unsigned long long (&acc)[TM][TN]) {
#pragma unroll
    for (int q = 0; q < NQ; ++q) {
        ulonglong2 a[TM], b[TN];
#pragma unroll
        for (int i = 0; i < TM; ++i)
            a[i] = *reinterpret_cast<const ulonglong2*>(Ap + (tr + 16 * i) * AST + q * 4);
#pragma unroll
        for (int j = 0; j < TN; ++j)
            b[j] = *reinterpret_cast<const ulonglong2*>(Bp + (tc + 16 * j) * BST + q * 4);
#pragma unroll
        for (int i = 0; i < TM; ++i)
#pragma unroll
            for (int j = 0; j < TN; ++j) {
                ffma2(acc[i][j], a[i].x, b[j].x);
                ffma2(acc[i][j], a[i].y, b[j].y);
            }
    }
}

// ---------------------------------------------------------------------------
// init: zero h(t=0) and barrier counter
// ---------------------------------------------------------------------------
__global__ void init_kernel() {
    int i = blockIdx.x * blockDim.x + threadIdx.x;
    if (i < BSZ * HDIM) g_h0[i] = 0.0f;
    if (i == 0) g_arrive = 0u;
}

// ---------------------------------------------------------------------------
// x_proj GEMM: C[16384,4096] = inp[16384,512] @ w_ih[4096,512]^T + bias
// BM=128, BN=64, KC=32 (8 quads), 256 thr, TM=8, TN=4, stride 36.
// ---------------------------------------------------------------------------
__global__ __launch_bounds__(256) void xproj_kernel(const float* __restrict__ inp,
                                                    const float* __restrict__ w_ih,
                                                    const float* __restrict__ bias) {
    constexpr int KC = 32, SKC = 36, TM = 8, TN = 4;
    __shared__ float As[128 * SKC];
    __shared__ float Bs[64 * SKC];
    const int tid = threadIdx.x;
    const int tr = tid >> 4, tc = tid & 15;
    const int row0 = blockIdx.y * 128;
    const int col0 = blockIdx.x * 64;

    unsigned long long acc[TM][TN];
#pragma unroll
    for (int i = 0; i < TM; ++i)
#pragma unroll
        for (int j = 0; j < TN; ++j) acc[i][j] = 0ull;

    for (int k0 = 0; k0 < IDIM; k0 += KC) {
#pragma unroll
        for (int v = 0; v < 4; ++v) {           // A: 128*8 = 1024 float4
            int id = tid + v * 256;
            int r = id >> 3, kq = id & 7;
            *reinterpret_cast<float4*>(As + r * SKC + kq * 4) =
                *reinterpret_cast<const float4*>(inp + (size_t)(row0 + r) * IDIM + k0 + kq * 4);
        }
#pragma unroll
        for (int v = 0; v < 2; ++v) {           // B: 64*8 = 512 float4
            int id = tid + v * 256;
            int r = id >> 3, kq = id & 7;
            *reinterpret_cast<float4*>(Bs + r * SKC + kq * 4) =
                *reinterpret_cast<const float4*>(w_ih + (size_t)(col0 + r) * IDIM + k0 + kq * 4);
        }
        __syncthreads();
        mac_f4<TM, TN, KC / 4, SKC, SKC>(As, Bs, tr, tc, acc);
        __syncthreads();
    }

#pragma unroll
    for (int j = 0; j < TN; ++j) {
        int c = col0 + tc + 16 * j;
        float bv = bias[c];
#pragma unroll
        for (int i = 0; i < TM; ++i) {
            int r = row0 + tr + 16 * i;
            g_xproj[(size_t)r * G4 + c] = pair_sum(acc[i][j]) + bv;
        }
    }
}

// ---------------------------------------------------------------------------
// Persistent recurrent kernel. 128 blocks x 512 threads.
// Block bx owns hidden cols [bx*8, bx*8+8) across all 4 gates (32 w_hh rows),
// cached in SMEM for all 320 steps. Two 256-thread halves split K=1024.
// h streamed per step via cp.async double-buffered 64-wide chunks.
// c lives in a register (fixed per-thread mapping). Grid barrier per step.
// ---------------------------------------------------------------------------
constexpr int WS_STRIDE = 1028;                    // = 1024+4 words (≡4 banks)
constexpr int WS_SIZE   = 32 * WS_STRIDE;          // 32896 floats
constexpr int AS_STRIDE = 68;                      // = 64+4 words
constexpr int AS_CHUNK  = 64 * AS_STRIDE;          // 4352 floats per (buf,half)
constexpr int AS_SIZE   = 2 * 2 * AS_CHUNK;        // 17408
constexpr int GB_HALF   = 64 * 33;                 // 2112
constexpr int GB_SIZE   = 2 * GB_HALF;             // 4224
constexpr int SMEM_FLOATS = WS_SIZE + AS_SIZE + GB_SIZE;          // 54528
constexpr size_t SMEM_BYTES = (size_t)SMEM_FLOATS * 4;            // 218112 B

__global__ __launch_bounds__(512, 1) void lstm_persist(const float* __restrict__ w_hh,
                                                       const float* __restrict__ bias) {
    extern __shared__ float sm[];
    float* Ws = sm;                    // [32][1028]
    float* As = sm + WS_SIZE;          // [2 buf][2 half][64][68]
    float* Gb = As + AS_SIZE;          // [2 half][64][33]

    const int tid  = threadIdx.x;
    const int half = tid >> 8;         // K-split half
    const int wtid = tid & 255;
    const int tr   = wtid >> 4;        // 0..15 (batch rows tr+16i)
    const int tc   = wtid & 15;        // 0..15 (gate cols tc+16j)
    const int j0   = blockIdx.x * 8;

    // pointwise mapping (fixed across steps -> c in register)
    const int pb = tid >> 3;           // batch 0..63
    const int pj = tid & 7;            // hidden col offset 0..7
    float c_reg = 0.0f;

    // ---- one-time: cache this block's 32 w_hh rows (full K) in SMEM ----
    for (int i = tid; i < 32 * 256; i += 512) {        // 8192 float4
        int row = i >> 8, q = i & 255;
        int grow = (row >> 3) * HDIM + j0 + (row & 7); // gate*H + j0 + jj
        *reinterpret_cast<float4*>(Ws + row * WS_STRIDE + q * 4) =
            *reinterpret_cast<const float4*>(w_hh + (size_t)grow * HDIM + q * 4);
    }
    const uint32_t as_base = (uint32_t)__cvta_generic_to_shared(As);
    __syncthreads();

    for (int t = 0; t < TT; ++t) {
        const float* __restrict__ hin = (t & 1) ? g_h1 : g_h0;
        float* __restrict__ hout      = (t & 1) ? g_h0 : g_h1;

        // prefetch x_proj gate values for this thread's pointwise element
        float xg[4];
        const float* xr = (t < ILEN) ? (g_xproj + ((size_t)pb * ILEN + t) * G4) : bias;
#pragma unroll
        for (int g = 0; g < 4; ++g) xg[g] = __ldg(xr + g * HDIM + j0 + pj);

        unsigned long long acc[4][2];
#pragma unroll
        for (int i = 0; i < 4; ++i) { acc[i][0] = 0ull; acc[i][1] = 0ull; }

        // prologue: chunk 0, both halves (2048 float4, 4 per thread)
#pragma unroll
        for (int v = 0; v < 4; ++v) {
            int id = tid + v * 512;
            int hh = id >> 10, rem = id & 1023;
            int r = rem >> 4, q = rem & 15;
            cp_async16(as_base + (uint32_t)((hh * AS_CHUNK + r * AS_STRIDE + q * 4) * 4),
                       hin + (size_t)r * HDIM + hh * 512 + q * 4);
        }
        cp_commit();

#pragma unroll 2
        for (int kc = 0; kc < 8; ++kc) {
            if (kc < 7) {
#pragma unroll
                for (int v = 0; v < 4; ++v) {
                    int id = tid + v * 512;
                    int hh = id >> 10, rem = id & 1023;
                    int r = rem >> 4, q = rem & 15;
                    int buf = (kc + 1) & 1;
                    cp_async16(as_base + (uint32_t)(((buf * 2 + hh) * AS_CHUNK +
                                                     r * AS_STRIDE + q * 4) * 4),
                               hin + (size_t)r * HDIM + hh * 512 + (kc + 1) * 64 + q * 4);
                }
                cp_commit();
                cp_wait<1>();
            } else {
                cp_wait<0>();
            }
            __syncthreads();
            const float* Ap = As + ((kc & 1) * 2 + half) * AS_CHUNK;
            const float* Wp = Ws + half * 512 + kc * 64;
            mac_f4<4, 2, 16, AS_STRIDE, WS_STRIDE>(Ap, Wp, tr, tc, acc);
            __syncthreads();   // protect buf before next cp.async overwrite
        }

        // dump K-split partials
        float* gb = Gb + half * GB_HALF;
#pragma unroll
        for (int i = 0; i < 4; ++i)
#pragma unroll
            for (int j = 0; j < 2; ++j)
                gb[(tr + 16 * i) * 33 + (tc + 16 * j)] = pair_sum(acc[i][j]);
        __syncthreads();

        // pointwise LSTM update: 512 elements, 1 per thread
        float pre[4];
#pragma unroll
        for (int g = 0; g < 4; ++g)
            pre[g] = Gb[pb * 33 + g * 8 + pj] + Gb[GB_HALF + pb * 33 + g * 8 + pj] + xg[g];
        float ig = sigmoidf_(pre[0]);
        float fg = sigmoidf_(pre[1]);
        float gg = tanhf(pre[2]);
        float og = sigmoidf_(pre[3]);
        float cn = fg * c_reg + ig * gg;
        c_reg = cn;
        float hn = og * tanhf(cn);
        int hidx = pb * HDIM + j0 + pj;
        hout[hidx] = hn;
        if (t >= ILEN)
            g_hs[(size_t)(t - ILEN) * (BSZ * HDIM) + hidx] = hn;

        // ---- grid barrier (sense-free monotonic counter) ----
        __threadfence();
        __syncthreads();
        if (tid == 0) {
            atomicAdd(&g_arrive, 1u);
            unsigned target = (unsigned)NBLK * (unsigned)(t + 1);
            while (*(volatile unsigned*)&g_arrive < target) { }
        }
        __syncthreads();
        __threadfence();
    }
}

// ---------------------------------------------------------------------------
// classifier: out[b][tt][o] = sigmoid(hs_row . clf_w[o] + clf_b[o])
// rows = tt*64 + b. BM=64, BN=64, KC=64 (16 quads), TM=4, TN=4, stride 68.
// ---------------------------------------------------------------------------
__global__ __launch_bounds__(256) void clf_kernel(const float* __restrict__ clf_w,
                                                  const float* __restrict__ clf_b,
                                                  float* __restrict__ out) {
    constexpr int KC = 64, SKC = 68, TM = 4, TN = 4;
    __shared__ float As[64 * SKC];
    __shared__ float Bs[64 * SKC];
    const int tid = threadIdx.x;
    const int tr = tid >> 4, tc = tid & 15;
    const int row0 = blockIdx.y * 64;
    const int col0 = blockIdx.x * 64;

    unsigned long long acc[TM][TN];
#pragma unroll
    for (int i = 0; i < TM; ++i)
#pragma unroll
        for (int j = 0; j < TN; ++j) acc[i][j] = 0ull;

    for (int k0 = 0; k0 < HDIM; k0 += KC) {
#pragma unroll
        for (int v = 0; v < 4; ++v) {           // 64*16 = 1024 float4
            int id = tid + v * 256;
            int r = id >> 4, kq = id & 15;
            *reinterpret_cast<float4*>(As + r * SKC + kq * 4) =
                *reinterpret_cast<const float4*>(g_hs + (size_t)(row0 + r) * HDIM + k0 + kq * 4);
        }
#pragma unroll
        for (int v = 0; v < 4; ++v) {
            int id = tid + v * 256;
            int r = id >> 4, kq = id & 15;
            *reinterpret_cast<float4*>(Bs + r * SKC + kq * 4) =
                *reinterpret_cast<const float4*>(clf_w + (size_t)(col0 + r) * HDIM + k0 + kq * 4);
        }
        __syncthreads();
        mac_f4<TM, TN, KC / 4, SKC, SKC>(As, Bs, tr, tc, acc);
        __syncthreads();
    }

#pragma unroll
    for (int j = 0; j < TN; ++j) {
        int o = col0 + tc + 16 * j;
        float bv = clf_b[o];
#pragma unroll
        for (int i = 0; i < TM; ++i) {
            int r  = row0 + tr + 16 * i;
            int tt = r >> 6;
            int b  = r & 63;
            out[((size_t)b * TLEN + tt) * ODIM + o] =
                1.0f / (1.0f + expf(-(pair_sum(acc[i][j]) + bv)));
        }
    }
}

// ---------------------------------------------------------------------------
// launch (graph-capturable: kernel launches only, default stream)
// Inputs (metadata order): inp, tlen, w_ih, w_hh, b, clf_w, clf_b
// ---------------------------------------------------------------------------
extern "C" void kernel_launch(void* const* d_in, const int* in_sizes, int n_in,
                              void* d_out, int out_size) {
    const float* inp   = (const float*)d_in[0];
    // d_in[1] = tlen (int32) — fixed at 64
    const float* w_ih  = (const float*)d_in[2];
    const float* w_hh  = (const float*)d_in[3];
    const float* bias  = (const float*)d_in[4];
    const float* clf_w = (const float*)d_in[5];
    const float* clf_b = (const float*)d_in[6];
    float* out = (float*)d_out;

    cudaFuncSetAttribute(lstm_persist, cudaFuncAttributeMaxDynamicSharedMemorySize,
                         (int)SMEM_BYTES);

    init_kernel<<<(BSZ * HDIM + 255) / 256, 256>>>();
    xproj_kernel<<<dim3(G4 / 64, (BSZ * ILEN) / 128), 256>>>(inp, w_ih, bias);
    lstm_persist<<<NBLK, 512, SMEM_BYTES>>>(w_hh, bias);
    clf_kernel<<<dim3(ODIM / 64, (TLEN * BSZ) / 64), 256>>>(clf_w, clf_b, out);
}

// round 8
// speedup vs baseline: 1.4309x; 1.0906x over previous
#include <cuda_runtime.h>
#include <math.h>
#include <stdint.h>

// ---------------------------------------------------------------------------
// LSTM_88716844466217 : B=64, ILEN=256, TLEN=64 (T=320), IDIM=512, HDIM=1024,
// ODIM=128. fp32, packed fma.rn.f32x2.
// R8: xproj = 3-buffer cp.async pipeline @ 2 CTAs/SM;
//     persist = TM4xTN4 4-way K-split, 3-buffer h streaming, 1 sync/chunk.
// ---------------------------------------------------------------------------

constexpr int BSZ  = 64;
constexpr int ILEN = 256;
constexpr int TLEN = 64;
constexpr int TT   = ILEN + TLEN;   // 320
constexpr int IDIM = 512;
constexpr int HDIM = 1024;
constexpr int G4   = 4 * HDIM;      // 4096
constexpr int ODIM = 128;
constexpr int NBLK = 128;           // persistent blocks (1/SM, all resident)

// Scratch (device globals: allocation-free per harness rules)
__device__ float g_xproj[(size_t)BSZ * ILEN * G4];   // [b*ILEN+t][4096], bias included
__device__ float g_h0[BSZ * HDIM];
__device__ float g_h1[BSZ * HDIM];
__device__ float g_hs[(size_t)TLEN * BSZ * HDIM];    // h for t in [ILEN, TT)
__device__ unsigned g_arrive;                         // grid barrier counter

#define DINL __device__ __forceinline__

DINL void ffma2(unsigned long long &d, unsigned long long a, unsigned long long b) {
    asm("fma.rn.f32x2 %0, %1, %2, %0;" : "+l"(d) : "l"(a), "l"(b));
}
DINL float pair_sum(unsigned long long v) {
    return __uint_as_float((unsigned)(v & 0xffffffffu)) +
           __uint_as_float((unsigned)(v >> 32));
}
DINL float sigmoidf_(float x) { return 1.0f / (1.0f + __expf(-x)); }

DINL void cp_async16(uint32_t saddr, const float* gptr) {
    asm volatile("cp.async.cg.shared.global [%0], [%1], 16;" :: "r"(saddr), "l"(gptr));
}
DINL void cp_commit() { asm volatile("cp.async.commit_group;"); }
template<int N> DINL void cp_wait() { asm volatile("cp.async.wait_group %0;" :: "n"(N)); }

// Generalized float4 (LDS.128) MAC.
// A rows: tr + RSI*i (i<TM), B rows: tc + CSJ*j (j<TN), NQ quads of 4 k each.
template<int TM, int TN, int NQ, int AST, int BST, int RSI, int CSJ>
DINL void mac_g(const float* __restrict__ Ap, const float* __restrict__ Bp,
                int tr, int tc, unsigned long long (&acc)[TM][TN]) {
#pragma unroll
    for (int q = 0; q < NQ; ++q) {
        ulonglong2 a[TM], b[TN];
#pragma unroll
        for (int i = 0; i < TM; ++i)
            a[i] = *reinterpret_cast<const ulonglong2*>(Ap + (tr + RSI * i) * AST + q * 4);
#pragma unroll
        for (int j = 0; j < TN; ++j)
            b[j] = *reinterpret_cast<const ulonglong2*>(Bp + (tc + CSJ * j) * BST + q * 4);
#pragma unroll
        for (int i = 0; i < TM; ++i)
#pragma unroll
            for (int j = 0; j < TN; ++j) {
                ffma2(acc[i][j], a[i].x, b[j].x);
                ffma2(acc[i][j], a[i].y, b[j].y);
            }
    }
}

// ---------------------------------------------------------------------------
// init: zero h(t=0) and barrier counter
// ---------------------------------------------------------------------------
__global__ void init_kernel() {
    int i = blockIdx.x * blockDim.x + threadIdx.x;
    if (i < BSZ * HDIM) g_h0[i] = 0.0f;
    if (i == 0) g_arrive = 0u;
}

// ---------------------------------------------------------------------------
// x_proj GEMM: C[16384,4096] = inp[16384,512] @ w_ih[4096,512]^T + bias
// BM=128, BN=64, KC=32 (8 quads), 256 thr, TM=8, TN=4.
// 3-buffer cp.async pipeline, ONE syncthreads per K-tile, 2 CTAs/SM.
// ---------------------------------------------------------------------------
constexpr int XP_SKC   = 36;                       // 32+4, bank-safe, 16B rows
constexpr int XP_ABUF  = 128 * XP_SKC;             // 4608 floats
constexpr int XP_BBUF  = 64 * XP_SKC;              // 2304 floats
constexpr int XP_NT    = IDIM / 32;                // 16 K-tiles
constexpr size_t XP_SMEM = (size_t)(3 * XP_ABUF + 3 * XP_BBUF) * 4;  // 82944 B

__global__ __launch_bounds__(256, 2) void xproj_kernel(const float* __restrict__ inp,
                                                       const float* __restrict__ w_ih,
                                                       const float* __restrict__ bias) {
    constexpr int TM = 8, TN = 4;
    extern __shared__ float sm[];
    float* As = sm;                    // [3][128][36]
    float* Bs = sm + 3 * XP_ABUF;      // [3][64][36]

    const int tid = threadIdx.x;
    const int tr = tid >> 4, tc = tid & 15;
    const int row0 = blockIdx.y * 128;
    const int col0 = blockIdx.x * 64;
    const uint32_t sa = (uint32_t)__cvta_generic_to_shared(As);
    const uint32_t sb = (uint32_t)__cvta_generic_to_shared(Bs);

    unsigned long long acc[TM][TN];
#pragma unroll
    for (int i = 0; i < TM; ++i)
#pragma unroll
        for (int j = 0; j < TN; ++j) acc[i][j] = 0ull;

    auto issue = [&](int kt, int buf) {
#pragma unroll
        for (int v = 0; v < 4; ++v) {              // A: 1024 float4
            int id = tid + v * 256;
            int r = id >> 3, kq = id & 7;
            cp_async16(sa + (uint32_t)((buf * XP_ABUF + r * XP_SKC + kq * 4) * 4),
                       inp + (size_t)(row0 + r) * IDIM + kt * 32 + kq * 4);
        }
#pragma unroll
        for (int v = 0; v < 2; ++v) {              // B: 512 float4
            int id = tid + v * 256;
            int r = id >> 3, kq = id & 7;
            cp_async16(sb + (uint32_t)((buf * XP_BBUF + r * XP_SKC + kq * 4) * 4),
                       w_ih + (size_t)(col0 + r) * IDIM + kt * 32 + kq * 4);
        }
    };

    issue(0, 0); cp_commit();
    issue(1, 1); cp_commit();

    for (int kt = 0; kt < XP_NT; ++kt) {
        cp_wait<1>();
        __syncthreads();
        int buf = kt % 3;
        mac_g<TM, TN, 8, XP_SKC, XP_SKC, 16, 16>(As + buf * XP_ABUF, Bs + buf * XP_BBUF,
                                                 tr, tc, acc);
        if (kt + 2 < XP_NT) issue(kt + 2, (kt + 2) % 3);
        cp_commit();                                // empty groups ok, keeps count uniform
    }

#pragma unroll
    for (int j = 0; j < TN; ++j) {
        int c = col0 + tc + 16 * j;
        float bv = bias[c];
#pragma unroll
        for (int i = 0; i < TM; ++i) {
            int r = row0 + tr + 16 * i;
            g_xproj[(size_t)r * G4 + c] = pair_sum(acc[i][j]) + bv;
        }
    }
}

// ---------------------------------------------------------------------------
// Persistent recurrent kernel. 128 blocks x 512 threads.
// Block bx owns hidden cols [bx*8, bx*8+8) across all 4 gates (32 w_hh rows),
// cached in SMEM for all 320 steps. 4-way K-split: half q = tid>>7 owns
// k in {c*64 + q*16 .. +16} per 64-wide chunk; within a half, 16 tr x 8 tc
// threads compute TM=4 x TN=4 outputs (rows tr+16i, local cols tc+8j).
// h streamed per step via cp.async, 3 buffers, one sync per chunk.
// c lives in a register. Grid barrier per step.
// ---------------------------------------------------------------------------
constexpr int WS_STRIDE = 1028;                    // 1024+4 words
constexpr int WS_SIZE   = 32 * WS_STRIDE;          // 32896 floats
constexpr int AS_STRIDE = 68;                      // 64+4 words (16B-aligned rows)
constexpr int AS_CHUNK  = 64 * AS_STRIDE;          // 4352 floats per buffer
constexpr int AS_NBUF   = 3;
constexpr int AS_SIZE   = AS_NBUF * AS_CHUNK;      // 13056 floats (52224 B)
constexpr int GB_HALF   = 64 * 33;                 // 2112 floats
// Gb (4 halves x 2112 = 8448 floats = 33792 B) overlays the As buffers.
constexpr size_t LP_SMEM = (size_t)(WS_SIZE + AS_SIZE) * 4;       // 183808 B

__global__ __launch_bounds__(512, 1) void lstm_persist(const float* __restrict__ w_hh,
                                                       const float* __restrict__ bias) {
    extern __shared__ float sm[];
    float* Ws = sm;                    // [32][1028]
    float* As = sm + WS_SIZE;          // [3][64][68]
    float* Gb = As;                    // overlay, [4][64][33]

    const int tid  = threadIdx.x;
    const int q    = tid >> 7;         // K-split quarter 0..3
    const int htid = tid & 127;
    const int tc   = htid & 7;         // local col base 0..7
    const int tr   = htid >> 3;        // batch row base 0..15
    const int j0   = blockIdx.x * 8;

    // pointwise mapping (fixed across steps -> c in register)
    const int pb = tid >> 3;           // batch 0..63
    const int pj = tid & 7;            // hidden col offset 0..7
    float c_reg = 0.0f;

    // ---- one-time: cache this block's 32 w_hh rows (full K) in SMEM ----
    for (int i = tid; i < 32 * 256; i += 512) {        // 8192 float4
        int row = i >> 8, qq = i & 255;
        int grow = (row >> 3) * HDIM + j0 + (row & 7); // gate*H + j0 + jj
        *reinterpret_cast<float4*>(Ws + row * WS_STRIDE + qq * 4) =
            *reinterpret_cast<const float4*>(w_hh + (size_t)grow * HDIM + qq * 4);
    }
    const uint32_t as_base = (uint32_t)__cvta_generic_to_shared(As);
    __syncthreads();

    for (int t = 0; t < TT; ++t) {
        const float* __restrict__ hin = (t & 1) ? g_h1 : g_h0;
        float* __restrict__ hout      = (t & 1) ? g_h0 : g_h1;

        // prefetch x_proj gate values for this thread's pointwise element
        float xg[4];
        const float* xr = (t < ILEN) ? (g_xproj + ((size_t)pb * ILEN + t) * G4) : bias;
#pragma unroll
        for (int g = 0; g < 4; ++g) xg[g] = __ldg(xr + g * HDIM + j0 + pj);

        unsigned long long acc[4][4];
#pragma unroll
        for (int i = 0; i < 4; ++i)
#pragma unroll
            for (int j = 0; j < 4; ++j) acc[i][j] = 0ull;

        // h chunk streamer: 64 batch rows x 64 k  (1024 float4, 2/thread)
        auto issue = [&](int c, int buf) {
#pragma unroll
            for (int v = 0; v < 2; ++v) {
                int id = tid + v * 512;
                int r = id >> 4, q16 = id & 15;
                cp_async16(as_base + (uint32_t)((buf * AS_CHUNK + r * AS_STRIDE + q16 * 4) * 4),
                           hin + (size_t)r * HDIM + c * 64 + q16 * 4);
            }
        };

        issue(0, 0); cp_commit();
        issue(1, 1); cp_commit();

        for (int c = 0; c < 16; ++c) {
            cp_wait<1>();
            __syncthreads();
            const float* Ap = As + (c % 3) * AS_CHUNK + q * 16;
            const float* Wp = Ws + c * 64 + q * 16;
            mac_g<4, 4, 4, AS_STRIDE, WS_STRIDE, 16, 8>(Ap, Wp, tr, tc, acc);
            if (c + 2 < 16) issue(c + 2, (c + 2) % 3);
            cp_commit();
        }
        __syncthreads();                 // all mac done before Gb overlays As

        // dump K-split partials: Gb[q][batch][lcol], stride 33
        float* gb = Gb + q * GB_HALF;
#pragma unroll
        for (int i = 0; i < 4; ++i)
#pragma unroll
            for (int j = 0; j < 4; ++j)
                gb[(tr + 16 * i) * 33 + (tc + 8 * j)] = pair_sum(acc[i][j]);
        __syncthreads();

        // pointwise LSTM update: 512 elements, 1 per thread
        float pre[4];
#pragma unroll
        for (int g = 0; g < 4; ++g) {
            int off = pb * 33 + g * 8 + pj;
            pre[g] = xg[g] + Gb[off] + Gb[GB_HALF + off] +
                     Gb[2 * GB_HALF + off] + Gb[3 * GB_HALF + off];
        }
        float ig = sigmoidf_(pre[0]);
        float fg = sigmoidf_(pre[1]);
        float gg = tanhf(pre[2]);
        float og = sigmoidf_(pre[3]);
        float cn = fg * c_reg + ig * gg;
        c_reg = cn;
        float hn = og * tanhf(cn);
        int hidx = pb * HDIM + j0 + pj;
        hout[hidx] = hn;
        if (t >= ILEN)
            g_hs[(size_t)(t - ILEN) * (BSZ * HDIM) + hidx] = hn;

        // ---- grid barrier (monotonic counter) ----
        __threadfence();
        __syncthreads();
        if (tid == 0) {
            atomicAdd(&g_arrive, 1u);
            unsigned target = (unsigned)NBLK * (unsigned)(t + 1);
            while (*(volatile unsigned*)&g_arrive < target) { }
        }
        __syncthreads();
        __threadfence();
    }
}

// ---------------------------------------------------------------------------
// classifier: out[b][tt][o] = sigmoid(hs_row . clf_w[o] + clf_b[o])
// rows = tt*64 + b. BM=64, BN=64, KC=64 (16 quads), TM=4, TN=4, stride 68.
// ---------------------------------------------------------------------------
__global__ __launch_bounds__(256) void clf_kernel(const float* __restrict__ clf_w,
                                                  const float* __restrict__ clf_b,
                                                  float* __restrict__ out) {
    constexpr int KC = 64, SKC = 68, TM = 4, TN = 4;
    __shared__ float As[64 * SKC];
    __shared__ float Bs[64 * SKC];
    const int tid = threadIdx.x;
    const int tr = tid >> 4, tc = tid & 15;
    const int row0 = blockIdx.y * 64;
    const int col0 = blockIdx.x * 64;

    unsigned long long acc[TM][TN];
#pragma unroll
    for (int i = 0; i < TM; ++i)
#pragma unroll
        for (int j = 0; j < TN; ++j) acc[i][j] = 0ull;

    for (int k0 = 0; k0 < HDIM; k0 += KC) {
#pragma unroll
        for (int v = 0; v < 4; ++v) {           // 64*16 = 1024 float4
            int id = tid + v * 256;
            int r = id >> 4, kq = id & 15;
            *reinterpret_cast<float4*>(As + r * SKC + kq * 4) =
                *reinterpret_cast<const float4*>(g_hs + (size_t)(row0 + r) * HDIM + k0 + kq * 4);
        }
#pragma unroll
        for (int v = 0; v < 4; ++v) {
            int id = tid + v * 256;
            int r = id >> 4, kq = id & 15;
            *reinterpret_cast<float4*>(Bs + r * SKC + kq * 4) =
                *reinterpret_cast<const float4*>(clf_w + (size_t)(col0 + r) * HDIM + k0 + kq * 4);
        }
        __syncthreads();
        mac_g<TM, TN, KC / 4, SKC, SKC, 16, 16>(As, Bs, tr, tc, acc);
        __syncthreads();
    }

#pragma unroll
    for (int j = 0; j < TN; ++j) {
        int o = col0 + tc + 16 * j;
        float bv = clf_b[o];
#pragma unroll
        for (int i = 0; i < TM; ++i) {
            int r  = row0 + tr + 16 * i;
            int tt = r >> 6;
            int b  = r & 63;
            out[((size_t)b * TLEN + tt) * ODIM + o] =
                1.0f / (1.0f + expf(-(pair_sum(acc[i][j]) + bv)));
        }
    }
}

// ---------------------------------------------------------------------------
// launch (graph-capturable: kernel launches only, default stream)
// Inputs (metadata order): inp, tlen, w_ih, w_hh, b, clf_w, clf_b
// ---------------------------------------------------------------------------
extern "C" void kernel_launch(void* const* d_in, const int* in_sizes, int n_in,
                              void* d_out, int out_size) {
    const float* inp   = (const float*)d_in[0];
    // d_in[1] = tlen (int32) — fixed at 64
    const float* w_ih  = (const float*)d_in[2];
    const float* w_hh  = (const float*)d_in[3];
    const float* bias  = (const float*)d_in[4];
    const float* clf_w = (const float*)d_in[5];
    const float* clf_b = (const float*)d_in[6];
    float* out = (float*)d_out;

    cudaFuncSetAttribute(xproj_kernel, cudaFuncAttributeMaxDynamicSharedMemorySize,
                         (int)XP_SMEM);
    cudaFuncSetAttribute(lstm_persist, cudaFuncAttributeMaxDynamicSharedMemorySize,
                         (int)LP_SMEM);

    init_kernel<<<(BSZ * HDIM + 255) / 256, 256>>>();
    xproj_kernel<<<dim3(G4 / 64, (BSZ * ILEN) / 128), 256, XP_SMEM>>>(inp, w_ih, bias);
    lstm_persist<<<NBLK, 512, LP_SMEM>>>(w_hh, bias);
    clf_kernel<<<dim3(ODIM / 64, (TLEN * BSZ) / 64), 256>>>(clf_w, clf_b, out);
}

// round 11
// speedup vs baseline: 1.4957x; 1.0453x over previous
#include <cuda_runtime.h>
#include <math.h>
#include <stdint.h>

// ---------------------------------------------------------------------------
// LSTM_88716844466217 : B=64, ILEN=256, TLEN=64 (T=320), IDIM=512, HDIM=1024,
// ODIM=128. fp32, packed fma.rn.f32x2.
// R11: proven R8 global-barrier sync (verbatim) + KC=128 2-buffer persist
// pipeline (8 chunks/step, halved syncs) + exact cp.async group accounting.
// ---------------------------------------------------------------------------

constexpr int BSZ  = 64;
constexpr int ILEN = 256;
constexpr int TLEN = 64;
constexpr int TT   = ILEN + TLEN;   // 320
constexpr int IDIM = 512;
constexpr int HDIM = 1024;
constexpr int G4   = 4 * HDIM;      // 4096
constexpr int ODIM = 128;
constexpr int NBLK = 128;           // persistent blocks (1/SM, all resident)

// Scratch (device globals: allocation-free per harness rules)
__device__ float g_xproj[(size_t)BSZ * ILEN * G4];   // [b*ILEN+t][4096], bias included
__device__ float g_h0[BSZ * HDIM];
__device__ float g_h1[BSZ * HDIM];
__device__ float g_hs[(size_t)TLEN * BSZ * HDIM];    // h for t in [ILEN, TT)
__device__ unsigned g_arrive;                         // grid barrier counter

#define DINL __device__ __forceinline__

DINL void ffma2(unsigned long long &d, unsigned long long a, unsigned long long b) {
    asm("fma.rn.f32x2 %0, %1, %2, %0;" : "+l"(d) : "l"(a), "l"(b));
}
DINL float pair_sum(unsigned long long v) {
    return __uint_as_float((unsigned)(v & 0xffffffffu)) +
           __uint_as_float((unsigned)(v >> 32));
}
DINL float sigmoidf_(float x) { return 1.0f / (1.0f + __expf(-x)); }

DINL void cp_async16(uint32_t saddr, const float* gptr) {
    asm volatile("cp.async.cg.shared.global [%0], [%1], 16;" :: "r"(saddr), "l"(gptr));
}
DINL void cp_commit() { asm volatile("cp.async.commit_group;"); }
template<int N> DINL void cp_wait() { asm volatile("cp.async.wait_group %0;" :: "n"(N)); }

// Generalized float4 (LDS.128) MAC.
// A rows: tr + RSI*i (i<TM), B rows: tc + CSJ*j (j<TN), NQ quads of 4 k each.
template<int TM, int TN, int NQ, int AST, int BST, int RSI, int CSJ>
DINL void mac_g(const float* __restrict__ Ap, const float* __restrict__ Bp,
                int tr, int tc, unsigned long long (&acc)[TM][TN]) {
#pragma unroll
    for (int q = 0; q < NQ; ++q) {
        ulonglong2 a[TM], b[TN];
#pragma unroll
        for (int i = 0; i < TM; ++i)
            a[i] = *reinterpret_cast<const ulonglong2*>(Ap + (tr + RSI * i) * AST + q * 4);
#pragma unroll
        for (int j = 0; j < TN; ++j)
            b[j] = *reinterpret_cast<const ulonglong2*>(Bp + (tc + CSJ * j) * BST + q * 4);
#pragma unroll
        for (int i = 0; i < TM; ++i)
#pragma unroll
            for (int j = 0; j < TN; ++j) {
                ffma2(acc[i][j], a[i].x, b[j].x);
                ffma2(acc[i][j], a[i].y, b[j].y);
            }
    }
}

// ---------------------------------------------------------------------------
// init: zero h(t=0) and barrier counter
// ---------------------------------------------------------------------------
__global__ void init_kernel() {
    int i = blockIdx.x * blockDim.x + threadIdx.x;
    if (i < BSZ * HDIM) g_h0[i] = 0.0f;
    if (i == 0) g_arrive = 0u;
}

// ---------------------------------------------------------------------------
// x_proj GEMM: C[16384,4096] = inp[16384,512] @ w_ih[4096,512]^T + bias
// BM=128, BN=64, KC=32 (8 quads), 256 thr, TM=8, TN=4.
// 3-buffer cp.async pipeline, ONE syncthreads per K-tile, 2 CTAs/SM.
// ---------------------------------------------------------------------------
constexpr int XP_SKC   = 36;                       // 32+4, bank-safe, 16B rows
constexpr int XP_ABUF  = 128 * XP_SKC;             // 4608 floats
constexpr int XP_BBUF  = 64 * XP_SKC;              // 2304 floats
constexpr int XP_NT    = IDIM / 32;                // 16 K-tiles
constexpr size_t XP_SMEM = (size_t)(3 * XP_ABUF + 3 * XP_BBUF) * 4;  // 82944 B

__global__ __launch_bounds__(256, 2) void xproj_kernel(const float* __restrict__ inp,
                                                       const float* __restrict__ w_ih,
                                                       const float* __restrict__ bias) {
    constexpr int TM = 8, TN = 4;
    extern __shared__ float sm[];
    float* As = sm;                    // [3][128][36]
    float* Bs = sm + 3 * XP_ABUF;      // [3][64][36]

    const int tid = threadIdx.x;
    const int tr = tid >> 4, tc = tid & 15;
    const int row0 = blockIdx.y * 128;
    const int col0 = blockIdx.x * 64;
    const uint32_t sa = (uint32_t)__cvta_generic_to_shared(As);
    const uint32_t sb = (uint32_t)__cvta_generic_to_shared(Bs);

    unsigned long long acc[TM][TN];
#pragma unroll
    for (int i = 0; i < TM; ++i)
#pragma unroll
        for (int j = 0; j < TN; ++j) acc[i][j] = 0ull;

    auto issue = [&](int kt, int buf) {
#pragma unroll
        for (int v = 0; v < 4; ++v) {              // A: 1024 float4
            int id = tid + v * 256;
            int r = id >> 3, kq = id & 7;
            cp_async16(sa + (uint32_t)((buf * XP_ABUF + r * XP_SKC + kq * 4) * 4),
                       inp + (size_t)(row0 + r) * IDIM + kt * 32 + kq * 4);
        }
#pragma unroll
        for (int v = 0; v < 2; ++v) {              // B: 512 float4
            int id = tid + v * 256;
            int r = id >> 3, kq = id & 7;
            cp_async16(sb + (uint32_t)((buf * XP_BBUF + r * XP_SKC + kq * 4) * 4),
                       w_ih + (size_t)(col0 + r) * IDIM + kt * 32 + kq * 4);
        }
    };

    issue(0, 0); cp_commit();
    issue(1, 1); cp_commit();

    for (int kt = 0; kt < XP_NT; ++kt) {
        // pending real groups here: {kt, kt+1} (no empty commits anywhere)
        if (kt < XP_NT - 1) cp_wait<1>(); else cp_wait<0>();
        __syncthreads();                 // buffer kt ready; all warps done mac(kt-1)
        if (kt + 2 < XP_NT) { issue(kt + 2, (kt + 2) % 3); cp_commit(); }
        int buf = kt % 3;
        mac_g<TM, TN, 8, XP_SKC, XP_SKC, 16, 16>(As + buf * XP_ABUF, Bs + buf * XP_BBUF,
                                                 tr, tc, acc);
    }

#pragma unroll
    for (int j = 0; j < TN; ++j) {
        int c = col0 + tc + 16 * j;
        float bv = bias[c];
#pragma unroll
        for (int i = 0; i < TM; ++i) {
            int r = row0 + tr + 16 * i;
            g_xproj[(size_t)r * G4 + c] = pair_sum(acc[i][j]) + bv;
        }
    }
}

// ---------------------------------------------------------------------------
// Persistent recurrent kernel. 128 blocks x 512 threads.
// Block bx owns hidden cols [bx*8, bx*8+8) across all 4 gates (32 w_hh rows),
// cached in SMEM for all 320 steps. 4-way K-split (quarter q = tid>>7 owns
// k subrange q*32..q*32+32 per 128-wide chunk); TM=4 x TN=4 per thread.
// h streamed per step via cp.async: 8 chunks of 128 k, 2 buffers,
// one syncthreads per chunk. c lives in a register.
// Inter-block sync: R8-proven global barrier (fence/sync/atomic-spin/sync/fence).
// ---------------------------------------------------------------------------
constexpr int WS_STRIDE = 1028;                    // 1024+4 words
constexpr int WS_SIZE   = 32 * WS_STRIDE;          // 32896 floats (131584 B)
constexpr int AS_STRIDE = 132;                     // 128+4 words (16B-aligned rows)
constexpr int AS_CHUNK  = 64 * AS_STRIDE;          // 8448 floats per buffer
constexpr int AS_SIZE   = 2 * AS_CHUNK;            // 16896 floats (67584 B)
constexpr int GB_HALF   = 64 * 33;                 // 2112 floats
// Gb (4 x 2112 = 8448 floats) overlays the As buffers (sync-separated).
constexpr size_t LP_SMEM = (size_t)(WS_SIZE + AS_SIZE) * 4;       // 199168 B

__global__ __launch_bounds__(512, 1) void lstm_persist(const float* __restrict__ w_hh,
                                                       const float* __restrict__ bias) {
    extern __shared__ float sm[];
    float* Ws = sm;                    // [32][1028]
    float* As = sm + WS_SIZE;          // [2][64][132]
    float* Gb = As;                    // overlay, [4][64][33]

    const int tid  = threadIdx.x;
    const int q    = tid >> 7;         // K-split quarter 0..3
    const int htid = tid & 127;
    const int tc   = htid & 7;         // local col base 0..7
    const int tr   = htid >> 3;        // batch row base 0..15
    const int j0   = blockIdx.x * 8;

    // pointwise mapping (fixed across steps -> c in register)
    const int pb = tid >> 3;           // batch 0..63
    const int pj = tid & 7;            // hidden col offset 0..7
    float c_reg = 0.0f;

    // ---- one-time: cache this block's 32 w_hh rows (full K) in SMEM ----
    for (int i = tid; i < 32 * 256; i += 512) {        // 8192 float4
        int row = i >> 8, qq = i & 255;
        int grow = (row >> 3) * HDIM + j0 + (row & 7); // gate*H + j0 + jj
        *reinterpret_cast<float4*>(Ws + row * WS_STRIDE + qq * 4) =
            *reinterpret_cast<const float4*>(w_hh + (size_t)grow * HDIM + qq * 4);
    }
    const uint32_t as_base = (uint32_t)__cvta_generic_to_shared(As);
    __syncthreads();

    for (int t = 0; t < TT; ++t) {
        const float* __restrict__ hin = (t & 1) ? g_h1 : g_h0;
        float* __restrict__ hout      = (t & 1) ? g_h0 : g_h1;

        // prefetch x_proj gate values for this thread's pointwise element
        float xg[4];
        const float* xr = (t < ILEN) ? (g_xproj + ((size_t)pb * ILEN + t) * G4) : bias;
#pragma unroll
        for (int g = 0; g < 4; ++g) xg[g] = __ldg(xr + g * HDIM + j0 + pj);

        unsigned long long acc[4][4];
#pragma unroll
        for (int i = 0; i < 4; ++i)
#pragma unroll
            for (int j = 0; j < 4; ++j) acc[i][j] = 0ull;

        // h chunk streamer: 64 batch rows x 128 k  (2048 float4, 4/thread)
        auto issue = [&](int c, int buf) {
#pragma unroll
            for (int v = 0; v < 4; ++v) {
                int id = tid + v * 512;
                int r = id >> 5, q32 = id & 31;
                cp_async16(as_base + (uint32_t)((buf * AS_CHUNK + r * AS_STRIDE + q32 * 4) * 4),
                           hin + (size_t)r * HDIM + c * 128 + q32 * 4);
            }
        };

        issue(0, 0); cp_commit();

        for (int c = 0; c < 8; ++c) {
            cp_wait<0>();                // chunk c (sole pending group) complete
            __syncthreads();             // all warps done mac(c-1): buf (c+1)&1 free
            if (c < 7) { issue(c + 1, (c + 1) & 1); cp_commit(); }
            const float* Ap = As + (c & 1) * AS_CHUNK + q * 32;
            const float* Wp = Ws + c * 128 + q * 32;
            mac_g<4, 4, 8, AS_STRIDE, WS_STRIDE, 16, 8>(Ap, Wp, tr, tc, acc);
        }
        __syncthreads();                 // all mac done before Gb overlays As

        // dump K-split partials: Gb[q][batch][lcol], stride 33
        float* gb = Gb + q * GB_HALF;
#pragma unroll
        for (int i = 0; i < 4; ++i)
#pragma unroll
            for (int j = 0; j < 4; ++j)
                gb[(tr + 16 * i) * 33 + (tc + 8 * j)] = pair_sum(acc[i][j]);
        __syncthreads();

        // pointwise LSTM update: 512 elements, 1 per thread
        float pre[4];
#pragma unroll
        for (int g = 0; g < 4; ++g) {
            int off = pb * 33 + g * 8 + pj;
            pre[g] = xg[g] + Gb[off] + Gb[GB_HALF + off] +
                     Gb[2 * GB_HALF + off] + Gb[3 * GB_HALF + off];
        }
        float ig = sigmoidf_(pre[0]);
        float fg = sigmoidf_(pre[1]);
        float gg = tanhf(pre[2]);
        float og = sigmoidf_(pre[3]);
        float cn = fg * c_reg + ig * gg;
        c_reg = cn;
        float hn = og * tanhf(cn);
        int hidx = pb * HDIM + j0 + pj;
        hout[hidx] = hn;
        if (t >= ILEN)
            g_hs[(size_t)(t - ILEN) * (BSZ * HDIM) + hidx] = hn;

        // ---- grid barrier (R8-proven protocol, verbatim) ----
        __threadfence();
        __syncthreads();
        if (tid == 0) {
            atomicAdd(&g_arrive, 1u);
            unsigned target = (unsigned)NBLK * (unsigned)(t + 1);
            while (*(volatile unsigned*)&g_arrive < target) { }
        }
        __syncthreads();
        __threadfence();
    }
}

// ---------------------------------------------------------------------------
// classifier: out[b][tt][o] = sigmoid(hs_row . clf_w[o] + clf_b[o])
// rows = tt*64 + b. BM=64, BN=64, KC=64 (16 quads), TM=4, TN=4, stride 68.
// ---------------------------------------------------------------------------
__global__ __launch_bounds__(256) void clf_kernel(const float* __restrict__ clf_w,
                                                  const float* __restrict__ clf_b,
                                                  float* __restrict__ out) {
    constexpr int KC = 64, SKC = 68, TM = 4, TN = 4;
    __shared__ float As[64 * SKC];
    __shared__ float Bs[64 * SKC];
    const int tid = threadIdx.x;
    const int tr = tid >> 4, tc = tid & 15;
    const int row0 = blockIdx.y * 64;
    const int col0 = blockIdx.x * 64;

    unsigned long long acc[TM][TN];
#pragma unroll
    for (int i = 0; i < TM; ++i)
#pragma unroll
        for (int j = 0; j < TN; ++j) acc[i][j] = 0ull;

    for (int k0 = 0; k0 < HDIM; k0 += KC) {
#pragma unroll
        for (int v = 0; v < 4; ++v) {           // 64*16 = 1024 float4
            int id = tid + v * 256;
            int r = id >> 4, kq = id & 15;
            *reinterpret_cast<float4*>(As + r * SKC + kq * 4) =
                *reinterpret_cast<const float4*>(g_hs + (size_t)(row0 + r) * HDIM + k0 + kq * 4);
        }
#pragma unroll
        for (int v = 0; v < 4; ++v) {
            int id = tid + v * 256;
            int r = id >> 4, kq = id & 15;
            *reinterpret_cast<float4*>(Bs + r * SKC + kq * 4) =
                *reinterpret_cast<const float4*>(clf_w + (size_t)(col0 + r) * HDIM + k0 + kq * 4);
        }
        __syncthreads();
        mac_g<TM, TN, KC / 4, SKC, SKC, 16, 16>(As, Bs, tr, tc, acc);
        __syncthreads();
    }

#pragma unroll
    for (int j = 0; j < TN; ++j) {
        int o = col0 + tc + 16 * j;
        float bv = clf_b[o];
#pragma unroll
        for (int i = 0; i < TM; ++i) {
            int r  = row0 + tr + 16 * i;
            int tt = r >> 6;
            int b  = r & 63;
            out[((size_t)b * TLEN + tt) * ODIM + o] =
                1.0f / (1.0f + expf(-(pair_sum(acc[i][j]) + bv)));
        }
    }
}

// ---------------------------------------------------------------------------
// launch (graph-capturable: kernel launches only, default stream)
// Inputs (metadata order): inp, tlen, w_ih, w_hh, b, clf_w, clf_b
// ---------------------------------------------------------------------------
extern "C" void kernel_launch(void* const* d_in, const int* in_sizes, int n_in,
                              void* d_out, int out_size) {
    const float* inp   = (const float*)d_in[0];
    // d_in[1] = tlen (int32) — fixed at 64
    const float* w_ih  = (const float*)d_in[2];
    const float* w_hh  = (const float*)d_in[3];
    const float* bias  = (const float*)d_in[4];
    const float* clf_w = (const float*)d_in[5];
    const float* clf_b = (const float*)d_in[6];
    float* out = (float*)d_out;

    cudaFuncSetAttribute(xproj_kernel, cudaFuncAttributeMaxDynamicSharedMemorySize,
                         (int)XP_SMEM);
    cudaFuncSetAttribute(lstm_persist, cudaFuncAttributeMaxDynamicSharedMemorySize,
                         (int)LP_SMEM);

    init_kernel<<<(BSZ * HDIM + 255) / 256, 256>>>();
    xproj_kernel<<<dim3(G4 / 64, (BSZ * ILEN) / 128), 256, XP_SMEM>>>(inp, w_ih, bias);
    lstm_persist<<<NBLK, 512, LP_SMEM>>>(w_hh, bias);
    clf_kernel<<<dim3(ODIM / 64, (TLEN * BSZ) / 64), 256>>>(clf_w, clf_b, out);
}

// round 12
// speedup vs baseline: 1.4974x; 1.0012x over previous
#include <cuda_runtime.h>
#include <math.h>
#include <stdint.h>

// ---------------------------------------------------------------------------
// LSTM_88716844466217 : B=64, ILEN=256, TLEN=64 (T=320), IDIM=512, HDIM=1024,
// ODIM=128. fp32, packed fma.rn.f32x2.
// R12: xproj register-pressure fix (k-pair MAC, LDS.64 operands, ~108 live
// regs < 128 cap) + coalesced smem-staged epilogue. persist/sync unchanged
// from the passing R11 kernel.
// ---------------------------------------------------------------------------

constexpr int BSZ  = 64;
constexpr int ILEN = 256;
constexpr int TLEN = 64;
constexpr int TT   = ILEN + TLEN;   // 320
constexpr int IDIM = 512;
constexpr int HDIM = 1024;
constexpr int G4   = 4 * HDIM;      // 4096
constexpr int ODIM = 128;
constexpr int NBLK = 128;           // persistent blocks (1/SM, all resident)

// Scratch (device globals: allocation-free per harness rules)
__device__ float g_xproj[(size_t)BSZ * ILEN * G4];   // [b*ILEN+t][4096], bias included
__device__ float g_h0[BSZ * HDIM];
__device__ float g_h1[BSZ * HDIM];
__device__ float g_hs[(size_t)TLEN * BSZ * HDIM];    // h for t in [ILEN, TT)
__device__ unsigned g_arrive;                         // grid barrier counter

#define DINL __device__ __forceinline__

DINL void ffma2(unsigned long long &d, unsigned long long a, unsigned long long b) {
    asm("fma.rn.f32x2 %0, %1, %2, %0;" : "+l"(d) : "l"(a), "l"(b));
}
DINL float pair_sum(unsigned long long v) {
    return __uint_as_float((unsigned)(v & 0xffffffffu)) +
           __uint_as_float((unsigned)(v >> 32));
}
DINL float sigmoidf_(float x) { return 1.0f / (1.0f + __expf(-x)); }

DINL void cp_async16(uint32_t saddr, const float* gptr) {
    asm volatile("cp.async.cg.shared.global [%0], [%1], 16;" :: "r"(saddr), "l"(gptr));
}
DINL void cp_commit() { asm volatile("cp.async.commit_group;"); }
template<int N> DINL void cp_wait() { asm volatile("cp.async.wait_group %0;" :: "n"(N)); }

// Generalized float4 (LDS.128) MAC (persist + clf).
// A rows: tr + RSI*i (i<TM), B rows: tc + CSJ*j (j<TN), NQ quads of 4 k each.
template<int TM, int TN, int NQ, int AST, int BST, int RSI, int CSJ>
DINL void mac_g(const float* __restrict__ Ap, const float* __restrict__ Bp,
                int tr, int tc, unsigned long long (&acc)[TM][TN]) {
#pragma unroll
    for (int q = 0; q < NQ; ++q) {
        ulonglong2 a[TM], b[TN];
#pragma unroll
        for (int i = 0; i < TM; ++i)
            a[i] = *reinterpret_cast<const ulonglong2*>(Ap + (tr + RSI * i) * AST + q * 4);
#pragma unroll
        for (int j = 0; j < TN; ++j)
            b[j] = *reinterpret_cast<const ulonglong2*>(Bp + (tc + CSJ * j) * BST + q * 4);
#pragma unroll
        for (int i = 0; i < TM; ++i)
#pragma unroll
            for (int j = 0; j < TN; ++j) {
                ffma2(acc[i][j], a[i].x, b[j].x);
                ffma2(acc[i][j], a[i].y, b[j].y);
            }
    }
}

// xproj MAC: TM=8, TN=4, k-pair granularity, LDS.64 operands.
// Live regs: 64 acc + 16 a + 8 b (+addr) ~ 108 < 128 cap -> no spills.
template<int NP, int AST, int BST>
DINL void mac_x(const float* __restrict__ Ap, const float* __restrict__ Bp,
                int tr, int tc, unsigned long long (&acc)[8][4]) {
#pragma unroll
    for (int p = 0; p < NP; ++p) {
        unsigned long long a[8], b[4];
#pragma unroll
        for (int i = 0; i < 8; ++i)
            a[i] = *reinterpret_cast<const unsigned long long*>(Ap + (tr + 16 * i) * AST + 2 * p);
#pragma unroll
        for (int j = 0; j < 4; ++j)
            b[j] = *reinterpret_cast<const unsigned long long*>(Bp + (tc + 16 * j) * BST + 2 * p);
#pragma unroll
        for (int i = 0; i < 8; ++i)
#pragma unroll
            for (int j = 0; j < 4; ++j)
                ffma2(acc[i][j], a[i], b[j]);
    }
}

// ---------------------------------------------------------------------------
// init: zero h(t=0) and barrier counter
// ---------------------------------------------------------------------------
__global__ void init_kernel() {
    int i = blockIdx.x * blockDim.x + threadIdx.x;
    if (i < BSZ * HDIM) g_h0[i] = 0.0f;
    if (i == 0) g_arrive = 0u;
}

// ---------------------------------------------------------------------------
// x_proj GEMM: C[16384,4096] = inp[16384,512] @ w_ih[4096,512]^T + bias
// BM=128, BN=64, KC=32, 256 thr, TM=8, TN=4.
// 3-buffer cp.async pipeline, ONE syncthreads per K-tile, 2 CTAs/SM.
// Epilogue staged through smem for coalesced STG.128.
// ---------------------------------------------------------------------------
constexpr int XP_SKC   = 36;                       // 32+4, bank-safe, 16B rows
constexpr int XP_ABUF  = 128 * XP_SKC;             // 4608 floats
constexpr int XP_BBUF  = 64 * XP_SKC;              // 2304 floats
constexpr int XP_NT    = IDIM / 32;                // 16 K-tiles
constexpr int XP_CST   = 68;                       // epilogue stage stride (64+4)
constexpr size_t XP_SMEM = (size_t)(3 * XP_ABUF + 3 * XP_BBUF) * 4;  // 82944 B
// epilogue stage needs 128*68 = 8704 floats <= 3*XP_ABUF = 13824  (overlay ok)

__global__ __launch_bounds__(256, 2) void xproj_kernel(const float* __restrict__ inp,
                                                       const float* __restrict__ w_ih,
                                                       const float* __restrict__ bias) {
    extern __shared__ float sm[];
    float* As = sm;                    // [3][128][36]
    float* Bs = sm + 3 * XP_ABUF;      // [3][64][36]

    const int tid = threadIdx.x;
    const int tr = tid >> 4, tc = tid & 15;
    const int row0 = blockIdx.y * 128;
    const int col0 = blockIdx.x * 64;
    const uint32_t sa = (uint32_t)__cvta_generic_to_shared(As);
    const uint32_t sb = (uint32_t)__cvta_generic_to_shared(Bs);

    unsigned long long acc[8][4];
#pragma unroll
    for (int i = 0; i < 8; ++i)
#pragma unroll
        for (int j = 0; j < 4; ++j) acc[i][j] = 0ull;

    auto issue = [&](int kt, int buf) {
#pragma unroll
        for (int v = 0; v < 4; ++v) {              // A: 1024 float4
            int id = tid + v * 256;
            int r = id >> 3, kq = id & 7;
            cp_async16(sa + (uint32_t)((buf * XP_ABUF + r * XP_SKC + kq * 4) * 4),
                       inp + (size_t)(row0 + r) * IDIM + kt * 32 + kq * 4);
        }
#pragma unroll
        for (int v = 0; v < 2; ++v) {              // B: 512 float4
            int id = tid + v * 256;
            int r = id >> 3, kq = id & 7;
            cp_async16(sb + (uint32_t)((buf * XP_BBUF + r * XP_SKC + kq * 4) * 4),
                       w_ih + (size_t)(col0 + r) * IDIM + kt * 32 + kq * 4);
        }
    };

    issue(0, 0); cp_commit();
    issue(1, 1); cp_commit();

    for (int kt = 0; kt < XP_NT; ++kt) {
        // pending real groups here: {kt, kt+1} (no empty commits anywhere)
        if (kt < XP_NT - 1) cp_wait<1>(); else cp_wait<0>();
        __syncthreads();                 // buffer kt ready; all warps done mac(kt-1)
        if (kt + 2 < XP_NT) { issue(kt + 2, (kt + 2) % 3); cp_commit(); }
        int buf = kt % 3;
        mac_x<16, XP_SKC, XP_SKC>(As + buf * XP_ABUF, Bs + buf * XP_BBUF, tr, tc, acc);
    }

    // ---- epilogue: stage tile in smem, store coalesced ----
    __syncthreads();                     // all mac done; As free for staging
    float* Cs = As;                      // [128][68]
#pragma unroll
    for (int j = 0; j < 4; ++j) {
        float bv = bias[col0 + tc + 16 * j];
#pragma unroll
        for (int i = 0; i < 8; ++i)
            Cs[(tr + 16 * i) * XP_CST + tc + 16 * j] = pair_sum(acc[i][j]) + bv;
    }
    __syncthreads();
#pragma unroll
    for (int v = 0; v < 8; ++v) {        // 128 rows x 16 float4 = 2048 stores
        int id = tid + v * 256;
        int r = id >> 4, c4 = id & 15;
        *reinterpret_cast<float4*>(g_xproj + (size_t)(row0 + r) * G4 + col0 + c4 * 4) =
            *reinterpret_cast<const float4*>(Cs + r * XP_CST + c4 * 4);
    }
}

// ---------------------------------------------------------------------------
// Persistent recurrent kernel (UNCHANGED from passing R11).
// 128 blocks x 512 threads; block bx owns hidden cols [bx*8, bx*8+8) across
// all 4 gates (32 w_hh rows) cached in SMEM; 4-way K-split, TM=4 x TN=4;
// h streamed via cp.async (8 chunks of 128 k, 2 buffers); c in register;
// R8-proven global barrier.
// ---------------------------------------------------------------------------
constexpr int WS_STRIDE = 1028;                    // 1024+4 words
constexpr int WS_SIZE   = 32 * WS_STRIDE;          // 32896 floats (131584 B)
constexpr int AS_STRIDE = 132;                     // 128+4 words (16B-aligned rows)
constexpr int AS_CHUNK  = 64 * AS_STRIDE;          // 8448 floats per buffer
constexpr int AS_SIZE   = 2 * AS_CHUNK;            // 16896 floats (67584 B)
constexpr int GB_HALF   = 64 * 33;                 // 2112 floats
// Gb (4 x 2112 = 8448 floats) overlays the As buffers (sync-separated).
constexpr size_t LP_SMEM = (size_t)(WS_SIZE + AS_SIZE) * 4;       // 199168 B

__global__ __launch_bounds__(512, 1) void lstm_persist(const float* __restrict__ w_hh,
                                                       const float* __restrict__ bias) {
    extern __shared__ float sm[];
    float* Ws = sm;                    // [32][1028]
    float* As = sm + WS_SIZE;          // [2][64][132]
    float* Gb = As;                    // overlay, [4][64][33]

    const int tid  = threadIdx.x;
    const int q    = tid >> 7;         // K-split quarter 0..3
    const int htid = tid & 127;
    const int tc   = htid & 7;         // local col base 0..7
    const int tr   = htid >> 3;        // batch row base 0..15
    const int j0   = blockIdx.x * 8;

    // pointwise mapping (fixed across steps -> c in register)
    const int pb = tid >> 3;           // batch 0..63
    const int pj = tid & 7;            // hidden col offset 0..7
    float c_reg = 0.0f;

    // ---- one-time: cache this block's 32 w_hh rows (full K) in SMEM ----
    for (int i = tid; i < 32 * 256; i += 512) {        // 8192 float4
        int row = i >> 8, qq = i & 255;
        int grow = (row >> 3) * HDIM + j0 + (row & 7); // gate*H + j0 + jj
        *reinterpret_cast<float4*>(Ws + row * WS_STRIDE + qq * 4) =
            *reinterpret_cast<const float4*>(w_hh + (size_t)grow * HDIM + qq * 4);
    }
    const uint32_t as_base = (uint32_t)__cvta_generic_to_shared(As);
    __syncthreads();

    for (int t = 0; t < TT; ++t) {
        const float* __restrict__ hin = (t & 1) ? g_h1 : g_h0;
        float* __restrict__ hout      = (t & 1) ? g_h0 : g_h1;

        // prefetch x_proj gate values for this thread's pointwise element
        // (issued here, consumed ~8us later at pointwise -> latency hidden)
        float xg[4];
        const float* xr = (t < ILEN) ? (g_xproj + ((size_t)pb * ILEN + t) * G4) : bias;
#pragma unroll
        for (int g = 0; g < 4; ++g) xg[g] = __ldg(xr + g * HDIM + j0 + pj);

        unsigned long long acc[4][4];
#pragma unroll
        for (int i = 0; i < 4; ++i)
#pragma unroll
            for (int j = 0; j < 4; ++j) acc[i][j] = 0ull;

        // h chunk streamer: 64 batch rows x 128 k  (2048 float4, 4/thread)
        auto issue = [&](int c, int buf) {
#pragma unroll
            for (int v = 0; v < 4; ++v) {
                int id = tid + v * 512;
                int r = id >> 5, q32 = id & 31;
                cp_async16(as_base + (uint32_t)((buf * AS_CHUNK + r * AS_STRIDE + q32 * 4) * 4),
                           hin + (size_t)r * HDIM + c * 128 + q32 * 4);
            }
        };

        issue(0, 0); cp_commit();

        for (int c = 0; c < 8; ++c) {
            cp_wait<0>();                // chunk c (sole pending group) complete
            __syncthreads();             // all warps done mac(c-1): buf (c+1)&1 free
            if (c < 7) { issue(c + 1, (c + 1) & 1); cp_commit(); }
            const float* Ap = As + (c & 1) * AS_CHUNK + q * 32;
            const float* Wp = Ws + c * 128 + q * 32;
            mac_g<4, 4, 8, AS_STRIDE, WS_STRIDE, 16, 8>(Ap, Wp, tr, tc, acc);
        }
        __syncthreads();                 // all mac done before Gb overlays As

        // dump K-split partials: Gb[q][batch][lcol], stride 33
        float* gb = Gb + q * GB_HALF;
#pragma unroll
        for (int i = 0; i < 4; ++i)
#pragma unroll
            for (int j = 0; j < 4; ++j)
                gb[(tr + 16 * i) * 33 + (tc + 8 * j)] = pair_sum(acc[i][j]);
        __syncthreads();

        // pointwise LSTM update: 512 elements, 1 per thread
        float pre[4];
#pragma unroll
        for (int g = 0; g < 4; ++g) {
            int off = pb * 33 + g * 8 + pj;
            pre[g] = xg[g] + Gb[off] + Gb[GB_HALF + off] +
                     Gb[2 * GB_HALF + off] + Gb[3 * GB_HALF + off];
        }
        float ig = sigmoidf_(pre[0]);
        float fg = sigmoidf_(pre[1]);
        float gg = tanhf(pre[2]);
        float og = sigmoidf_(pre[3]);
        float cn = fg * c_reg + ig * gg;
        c_reg = cn;
        float hn = og * tanhf(cn);
        int hidx = pb * HDIM + j0 + pj;
        hout[hidx] = hn;
        if (t >= ILEN)
            g_hs[(size_t)(t - ILEN) * (BSZ * HDIM) + hidx] = hn;

        // ---- grid barrier (R8-proven protocol, verbatim) ----
        __threadfence();
        __syncthreads();
        if (tid == 0) {
            atomicAdd(&g_arrive, 1u);
            unsigned target = (unsigned)NBLK * (unsigned)(t + 1);
            while (*(volatile unsigned*)&g_arrive < target) { }
        }
        __syncthreads();
        __threadfence();
    }
}

// ---------------------------------------------------------------------------
// classifier: out[b][tt][o] = sigmoid(hs_row . clf_w[o] + clf_b[o])
// rows = tt*64 + b. BM=64, BN=64, KC=64 (16 quads), TM=4, TN=4, stride 68.
// ---------------------------------------------------------------------------
__global__ __launch_bounds__(256) void clf_kernel(const float* __restrict__ clf_w,
                                                  const float* __restrict__ clf_b,
                                                  float* __restrict__ out) {
    constexpr int KC = 64, SKC = 68, TM = 4, TN = 4;
    __shared__ float As[64 * SKC];
    __shared__ float Bs[64 * SKC];
    const int tid = threadIdx.x;
    const int tr = tid >> 4, tc = tid & 15;
    const int row0 = blockIdx.y * 64;
    const int col0 = blockIdx.x * 64;

    unsigned long long acc[TM][TN];
#pragma unroll
    for (int i = 0; i < TM; ++i)
#pragma unroll
        for (int j = 0; j < TN; ++j) acc[i][j] = 0ull;

    for (int k0 = 0; k0 < HDIM; k0 += KC) {
#pragma unroll
        for (int v = 0; v < 4; ++v) {           // 64*16 = 1024 float4
            int id = tid + v * 256;
            int r = id >> 4, kq = id & 15;
            *reinterpret_cast<float4*>(As + r * SKC + kq * 4) =
                *reinterpret_cast<const float4*>(g_hs + (size_t)(row0 + r) * HDIM + k0 + kq * 4);
        }
#pragma unroll
        for (int v = 0; v < 4; ++v) {
            int id = tid + v * 256;
            int r = id >> 4, kq = id & 15;
            *reinterpret_cast<float4*>(Bs + r * SKC + kq * 4) =
                *reinterpret_cast<const float4*>(clf_w + (size_t)(col0 + r) * HDIM + k0 + kq * 4);
        }
        __syncthreads();
        mac_g<TM, TN, KC / 4, SKC, SKC, 16, 16>(As, Bs, tr, tc, acc);
        __syncthreads();
    }

#pragma unroll
    for (int j = 0; j < TN; ++j) {
        int o = col0 + tc + 16 * j;
        float bv = clf_b[o];
#pragma unroll
        for (int i = 0; i < TM; ++i) {
            int r  = row0 + tr + 16 * i;
            int tt = r >> 6;
            int b  = r & 63;
            out[((size_t)b * TLEN + tt) * ODIM + o] =
                1.0f / (1.0f + expf(-(pair_sum(acc[i][j]) + bv)));
        }
    }
}

// ---------------------------------------------------------------------------
// launch (graph-capturable: kernel launches only, default stream)
// Inputs (metadata order): inp, tlen, w_ih, w_hh, b, clf_w, clf_b
// ---------------------------------------------------------------------------
extern "C" void kernel_launch(void* const* d_in, const int* in_sizes, int n_in,
                              void* d_out, int out_size) {
    const float* inp   = (const float*)d_in[0];
    // d_in[1] = tlen (int32) — fixed at 64
    const float* w_ih  = (const float*)d_in[2];
    const float* w_hh  = (const float*)d_in[3];
    const float* bias  = (const float*)d_in[4];
    const float* clf_w = (const float*)d_in[5];
    const float* clf_b = (const float*)d_in[6];
    float* out = (float*)d_out;

    cudaFuncSetAttribute(xproj_kernel, cudaFuncAttributeMaxDynamicSharedMemorySize,
                         (int)XP_SMEM);
    cudaFuncSetAttribute(lstm_persist, cudaFuncAttributeMaxDynamicSharedMemorySize,
                         (int)LP_SMEM);

    init_kernel<<<(BSZ * HDIM + 255) / 256, 256>>>();
    xproj_kernel<<<dim3(G4 / 64, (BSZ * ILEN) / 128), 256, XP_SMEM>>>(inp, w_ih, bias);
    lstm_persist<<<NBLK, 512, LP_SMEM>>>(w_hh, bias);
    clf_kernel<<<dim3(ODIM / 64, (TLEN * BSZ) / 64), 256>>>(clf_w, clf_b, out);
}